// round 6
// baseline (speedup 1.0000x reference)
#include <cuda_runtime.h>

#define Nn 8192
#define Dd 16
#define Cc 8
#define Rr 64
#define NROWS (Cc + Dd * (Cc + 1))   // 152

// score scratch, split by row type (static device globals, allowed)
__device__ double  g_sc_curr[(size_t)Nn * Cc];        // j in [0,8)
__device__ double2 g_sc_nei [(size_t)Nn * 64];        // 128 nei rows as 64 pairs
__device__ double2 g_sc_head[(size_t)Nn * 8];         // 16 head rows as 8 pairs

// ---------------------------------------------------------------------------
// Kernel A: new_emb[n,r] = sum_d alpha[n,d]*msg[n,d,r] + curr_emb[n,0,r]
// ---------------------------------------------------------------------------
__global__ __launch_bounds__(256) void new_emb_kernel(
    const float* __restrict__ msg,
    const float* __restrict__ alpha,
    const float* __restrict__ curr_emb,
    float* __restrict__ out_emb)
{
    const int idx = blockIdx.x * 256 + threadIdx.x;   // 0 .. N*R-1
    const int n = idx >> 6;
    const int r = idx & 63;

    const float* m = msg + (size_t)n * Dd * Rr + r;
    const float* a = alpha + (size_t)n * Dd;

    float acc = 0.f;
    #pragma unroll
    for (int d = 0; d < Dd; d++) acc += a[d] * m[d * Rr];
    acc += curr_emb[(size_t)n * Dd * Rr + r];
    out_emb[idx] = acc;
}

// ---------------------------------------------------------------------------
// shared per-row score math: 8 diffs -> fp32 pairwise tree (identical order
// to prior rounds), then exact fp64 8-lane combine.
// ---------------------------------------------------------------------------
__device__ __forceinline__ float score_part(
    float4 a0, float4 a1, float4 s0, float4 s1, float4 ne0, float4 ne1)
{
    // term order identical to prior rounds: (a + s) - ne, s = (b + h)
    float d0 = (a0.x + s0.x) - ne0.x;
    float d1 = (a0.y + s0.y) - ne0.y;
    float d2 = (a0.z + s0.z) - ne0.z;
    float d3 = (a0.w + s0.w) - ne0.w;
    float d4 = (a1.x + s1.x) - ne1.x;
    float d5 = (a1.y + s1.y) - ne1.y;
    float d6 = (a1.z + s1.z) - ne1.z;
    float d7 = (a1.w + s1.w) - ne1.w;
    float q0 = fmaf(d0, d0, d1 * d1);
    float q1 = fmaf(d2, d2, d3 * d3);
    float q2 = fmaf(d4, d4, d5 * d5);
    float q3 = fmaf(d6, d6, d7 * d7);
    return (q0 + q1) + (q2 + q3);
}

__device__ __forceinline__ double combine8(double s) {
    s += __shfl_down_sync(0xffffffffu, s, 4);
    s += __shfl_down_sync(0xffffffffu, s, 2);
    s += __shfl_down_sync(0xffffffffu, s, 1);
    return s;
}

// ---------------------------------------------------------------------------
// Kernel B2 (the big streamer): nei rows. 8-lane group handles 2 consecutive
// rows (same head_rel d-row). __ldcs on zero-reuse streams, __ldg on reuse.
// ---------------------------------------------------------------------------
__global__ __launch_bounds__(256) void score_nei_kernel(
    const float* __restrict__ nei_node_mem,
    const float* __restrict__ nei_rel_mem,
    const float* __restrict__ head_rel_emb,
    const float* __restrict__ new_emb)
{
    const int gw   = (blockIdx.x * 256 + threadIdx.x) >> 5;
    const int lane = threadIdx.x & 31;
    const int sub  = lane >> 3;
    const int sl   = lane & 7;

    const int pr  = gw * 8 + sub * 2;     // first row of the pair (even)
    const int n   = pr >> 7;
    const int idx = pr & 127;             // even, pair never crosses d
    const int d   = idx >> 3;

    const float4* pa = (const float4*)(nei_node_mem + ((size_t)n * 128 + idx) * Rr);
    const float4* pb = (const float4*)(nei_rel_mem  + ((size_t)n * 128 + idx) * Rr);
    const float4* ph = (const float4*)(head_rel_emb + ((size_t)n * Dd + d) * Rr);
    const float4* pn = (const float4*)(new_emb + (size_t)n * Rr);

    const float4 ne0 = __ldg(&pn[sl]);
    const float4 ne1 = __ldg(&pn[8 + sl]);
    const float4 h0  = __ldg(&ph[sl]);
    const float4 h1  = __ldg(&ph[8 + sl]);

    const float4 a0 = __ldcs(&pa[sl]);
    const float4 a1 = __ldcs(&pa[8 + sl]);
    const float4 a2 = __ldcs(&pa[16 + sl]);
    const float4 a3 = __ldcs(&pa[24 + sl]);
    const float4 b0 = __ldcs(&pb[sl]);
    const float4 b1 = __ldcs(&pb[8 + sl]);
    const float4 b2 = __ldcs(&pb[16 + sl]);
    const float4 b3 = __ldcs(&pb[24 + sl]);

    // s = (b + h), element-wise fp32, same order as before
    float4 s0 = make_float4(b0.x + h0.x, b0.y + h0.y, b0.z + h0.z, b0.w + h0.w);
    float4 s1 = make_float4(b1.x + h1.x, b1.y + h1.y, b1.z + h1.z, b1.w + h1.w);
    float4 s2 = make_float4(b2.x + h0.x, b2.y + h0.y, b2.z + h0.z, b2.w + h0.w);
    float4 s3 = make_float4(b3.x + h1.x, b3.y + h1.y, b3.z + h1.z, b3.w + h1.w);

    double r0 = combine8((double)score_part(a0, a1, s0, s1, ne0, ne1));
    double r1 = combine8((double)score_part(a2, a3, s2, s3, ne0, ne1));

    if (sl == 0) g_sc_nei[((size_t)n * 128 + idx) >> 1] = make_double2(r0, r1);
}

// ---------------------------------------------------------------------------
// Kernel B1: curr rows (j<8): term = (a + b) - ne ; pair of rows per group.
// ---------------------------------------------------------------------------
__global__ __launch_bounds__(256) void score_curr_kernel(
    const float* __restrict__ curr_node_mem,
    const float* __restrict__ curr_rel_mem,
    const float* __restrict__ new_emb)
{
    const int gw   = (blockIdx.x * 256 + threadIdx.x) >> 5;
    const int lane = threadIdx.x & 31;
    const int sub  = lane >> 3;
    const int sl   = lane & 7;

    const int pr = gw * 8 + sub * 2;      // pair of curr rows (even)
    const int n  = pr >> 3;
    const int c  = pr & 7;                // even

    const float4* pa = (const float4*)(curr_node_mem + ((size_t)n * Dd * Cc + c) * Rr);
    const float4* pb = (const float4*)(curr_rel_mem  + ((size_t)n * Dd * Cc + c) * Rr);
    const float4* pn = (const float4*)(new_emb + (size_t)n * Rr);

    const float4 ne0 = __ldg(&pn[sl]);
    const float4 ne1 = __ldg(&pn[8 + sl]);

    const float4 a0 = __ldcs(&pa[sl]);
    const float4 a1 = __ldcs(&pa[8 + sl]);
    const float4 a2 = __ldcs(&pa[16 + sl]);
    const float4 a3 = __ldcs(&pa[24 + sl]);
    const float4 b0 = __ldcs(&pb[sl]);
    const float4 b1 = __ldcs(&pb[8 + sl]);
    const float4 b2 = __ldcs(&pb[16 + sl]);
    const float4 b3 = __ldcs(&pb[24 + sl]);

    double r0 = combine8((double)score_part(a0, a1, b0, b1, ne0, ne1));
    double r1 = combine8((double)score_part(a2, a3, b2, b3, ne0, ne1));

    if (sl == 0) {
        g_sc_curr[(size_t)n * Cc + c]     = r0;
        g_sc_curr[(size_t)n * Cc + c + 1] = r1;
    }
}

// ---------------------------------------------------------------------------
// Kernel B3: head rows (cc==8): term = (a + h) - ne ; pair (d, d+1) per group.
// ---------------------------------------------------------------------------
__global__ __launch_bounds__(256) void score_head_kernel(
    const float* __restrict__ head_emb,
    const float* __restrict__ head_rel_emb,
    const float* __restrict__ new_emb)
{
    const int gw   = (blockIdx.x * 256 + threadIdx.x) >> 5;
    const int lane = threadIdx.x & 31;
    const int sub  = lane >> 3;
    const int sl   = lane & 7;

    const int pr = gw * 8 + sub * 2;      // pair of head rows (even d)
    const int n  = pr >> 4;
    const int d  = pr & 15;               // even

    const float4* pa = (const float4*)(head_emb     + ((size_t)n * Dd + d) * Rr);
    const float4* ph = (const float4*)(head_rel_emb + ((size_t)n * Dd + d) * Rr);
    const float4* pn = (const float4*)(new_emb + (size_t)n * Rr);

    const float4 ne0 = __ldg(&pn[sl]);
    const float4 ne1 = __ldg(&pn[8 + sl]);

    const float4 a0 = __ldcs(&pa[sl]);
    const float4 a1 = __ldcs(&pa[8 + sl]);
    const float4 a2 = __ldcs(&pa[16 + sl]);
    const float4 a3 = __ldcs(&pa[24 + sl]);
    const float4 h0 = __ldg(&ph[sl]);
    const float4 h1 = __ldg(&ph[8 + sl]);
    const float4 h2 = __ldg(&ph[16 + sl]);
    const float4 h3 = __ldg(&ph[24 + sl]);

    double r0 = combine8((double)score_part(a0, a1, h0, h1, ne0, ne1));
    double r1 = combine8((double)score_part(a2, a3, h2, h3, ne0, ne1));

    if (sl == 0) g_sc_head[((size_t)n * Dd + d) >> 1] = make_double2(r0, r1);
}

// ---------------------------------------------------------------------------
// Kernel C: per-n topk (stable) + gather. Block per n, 256 threads.
// ---------------------------------------------------------------------------
__global__ __launch_bounds__(256) void topk_gather_kernel(
    const float* __restrict__ curr_node_mem,
    const float* __restrict__ curr_rel_mem,
    const float* __restrict__ nei_node_mem,
    const float* __restrict__ nei_rel_mem,
    const float* __restrict__ head_rel_emb,
    const float* __restrict__ head_emb,
    float* __restrict__ out_node,
    float* __restrict__ out_rel)
{
    const int n    = blockIdx.x;
    const int t    = threadIdx.x;
    const int w    = t >> 5;
    const int lane = t & 31;

    __shared__ double s_score[NROWS];
    __shared__ int    s_sel[Cc];

    if (t < NROWS) {
        double s;
        if (t < Cc) {
            s = g_sc_curr[(size_t)n * Cc + t];
        } else {
            const int j2 = t - Cc;
            const int d  = j2 / 9;
            const int cc = j2 - d * 9;
            if (cc < Cc) {
                const int idx = d * Cc + cc;
                const double2 p = g_sc_nei[((size_t)n * 128 + idx) >> 1];
                s = (idx & 1) ? p.y : p.x;
            } else {
                const double2 p = g_sc_head[((size_t)n * Dd + d) >> 1];
                s = (d & 1) ? p.y : p.x;
            }
        }
        s_score[t] = s;
    }
    __syncthreads();

    if (w == 0) {
        for (int k = 0; k < Cc; k++) {
            double bs = -1.0;
            int    bj = NROWS;
            for (int j = lane; j < NROWS; j += 32) {
                double s = s_score[j];
                if (s > bs || (s == bs && j < bj)) { bs = s; bj = j; }
            }
            #pragma unroll
            for (int off = 16; off; off >>= 1) {
                double os = __shfl_down_sync(0xffffffffu, bs, off);
                int    oj = __shfl_down_sync(0xffffffffu, bj, off);
                if (os > bs || (os == bs && oj < bj)) { bs = os; bj = oj; }
            }
            bj = __shfl_sync(0xffffffffu, bj, 0);
            if (lane == 0) { s_sel[k] = bj; s_score[bj] = -2.0; }
            __syncwarp();
        }
    }
    __syncthreads();

    // gather: warp w writes output row (n, w)
    // reference: f = n*C + topkind; nn = f/152, col = f%152 (cross-sample)
    const int jsel = s_sel[w];
    const int f    = n * Cc + jsel;
    const int nn   = f / NROWS;
    const int col  = f - nn * NROWS;
    const size_t gDR  = (size_t)nn * Dd * Rr;
    const size_t gDCR = (size_t)nn * Dd * Cc * Rr;

    float2 a, b;
    if (col < Cc) {
        a = ((const float2*)(curr_node_mem + gDCR + (size_t)col * Rr))[lane];
        b = ((const float2*)(curr_rel_mem  + gDCR + (size_t)col * Rr))[lane];
    } else {
        int c2 = col - Cc;
        int d  = c2 / 9;
        int cc = c2 - d * 9;
        float2 h = ((const float2*)(head_rel_emb + gDR + (size_t)d * Rr))[lane];
        if (cc < Cc) {
            a = ((const float2*)(nei_node_mem + gDCR + (size_t)(d * Cc + cc) * Rr))[lane];
            float2 bb = ((const float2*)(nei_rel_mem + gDCR + (size_t)(d * Cc + cc) * Rr))[lane];
            b.x = bb.x + h.x;  b.y = bb.y + h.y;
        } else {
            a = ((const float2*)(head_emb + gDR + (size_t)d * Rr))[lane];
            b = h;
        }
    }
    ((float2*)(out_node + ((size_t)n * Cc + w) * Rr))[lane] = a;
    ((float2*)(out_rel  + ((size_t)n * Cc + w) * Rr))[lane] = b;
}

// ---------------------------------------------------------------------------
extern "C" void kernel_launch(void* const* d_in, const int* in_sizes, int n_in,
                              void* d_out, int out_size)
{
    (void)in_sizes; (void)n_in; (void)out_size;
    const float* curr_emb      = (const float*)d_in[0];
    const float* alpha         = (const float*)d_in[1];
    const float* msg           = (const float*)d_in[2];
    const float* curr_node_mem = (const float*)d_in[3];
    const float* curr_rel_mem  = (const float*)d_in[4];
    const float* nei_node_mem  = (const float*)d_in[5];
    const float* nei_rel_mem   = (const float*)d_in[6];
    const float* head_rel_emb  = (const float*)d_in[7];
    const float* head_emb      = (const float*)d_in[8];

    float* out_emb  = (float*)d_out;                     // N*R
    float* out_node = out_emb  + (size_t)Nn * Rr;        // N*C*R
    float* out_rel  = out_node + (size_t)Nn * Cc * Rr;   // N*C*R

    // A: new_emb
    new_emb_kernel<<<(Nn * Rr) / 256, 256>>>(msg, alpha, curr_emb, out_emb);

    // B2: nei rows — 8192*128 rows, 8 rows per warp -> 131072 warps
    score_nei_kernel<<<(Nn * 128 / 8) / 8, 256>>>(nei_node_mem, nei_rel_mem,
                                                  head_rel_emb, out_emb);
    // B1: curr rows — 8192*8 rows, 8 per warp -> 8192 warps
    score_curr_kernel<<<(Nn * Cc / 8) / 8, 256>>>(curr_node_mem, curr_rel_mem,
                                                  out_emb);
    // B3: head rows — 8192*16 rows, 8 per warp -> 16384 warps
    score_head_kernel<<<(Nn * Dd / 8) / 8, 256>>>(head_emb, head_rel_emb,
                                                  out_emb);

    // C: topk + gather
    topk_gather_kernel<<<Nn, 256>>>(curr_node_mem, curr_rel_mem,
                                    nei_node_mem, nei_rel_mem,
                                    head_rel_emb, head_emb,
                                    out_node, out_rel);
}

// round 7
// speedup vs baseline: 1.0563x; 1.0563x over previous
#include <cuda_runtime.h>

#define Nn 8192
#define Dd 16
#define Cc 8
#define Rr 64
#define NROWS (Cc + Dd * (Cc + 1))   // 152

// block-range dispatch for the unified score kernel
#define NEI_BLOCKS  16384            // 8192*128 rows / 8 rows-per-warp / 8 warps
#define HEAD_BLOCKS 2048             // 8192*16 / 8 / 8
#define CURR_BLOCKS 1024             // 8192*8  / 8 / 8
#define B_BLOCKS (NEI_BLOCKS + HEAD_BLOCKS + CURR_BLOCKS)

// score scratch, split by row type (static device globals, allowed)
__device__ double  g_sc_curr[(size_t)Nn * Cc];
__device__ double2 g_sc_nei [(size_t)Nn * 64];
__device__ double2 g_sc_head[(size_t)Nn * 8];

// ---------------------------------------------------------------------------
// Kernel A: new_emb[n,r] = sum_d alpha[n,d]*msg[n,d,r] + curr_emb[n,0,r]
// ---------------------------------------------------------------------------
__global__ __launch_bounds__(256) void new_emb_kernel(
    const float* __restrict__ msg,
    const float* __restrict__ alpha,
    const float* __restrict__ curr_emb,
    float* __restrict__ out_emb)
{
    const int idx = blockIdx.x * 256 + threadIdx.x;   // 0 .. N*R-1
    const int n = idx >> 6;
    const int r = idx & 63;

    const float* m = msg + (size_t)n * Dd * Rr + r;
    const float* a = alpha + (size_t)n * Dd;

    float acc = 0.f;
    #pragma unroll
    for (int d = 0; d < Dd; d++) acc += a[d] * m[d * Rr];
    acc += curr_emb[(size_t)n * Dd * Rr + r];
    out_emb[idx] = acc;
}

// ---------------------------------------------------------------------------
// shared per-row score math (identical fp32 order to prior rounds)
// ---------------------------------------------------------------------------
__device__ __forceinline__ float score_part(
    float4 a0, float4 a1, float4 s0, float4 s1, float4 ne0, float4 ne1)
{
    float d0 = (a0.x + s0.x) - ne0.x;
    float d1 = (a0.y + s0.y) - ne0.y;
    float d2 = (a0.z + s0.z) - ne0.z;
    float d3 = (a0.w + s0.w) - ne0.w;
    float d4 = (a1.x + s1.x) - ne1.x;
    float d5 = (a1.y + s1.y) - ne1.y;
    float d6 = (a1.z + s1.z) - ne1.z;
    float d7 = (a1.w + s1.w) - ne1.w;
    float q0 = fmaf(d0, d0, d1 * d1);
    float q1 = fmaf(d2, d2, d3 * d3);
    float q2 = fmaf(d4, d4, d5 * d5);
    float q3 = fmaf(d6, d6, d7 * d7);
    return (q0 + q1) + (q2 + q3);
}

__device__ __forceinline__ double combine8(double s) {
    s += __shfl_down_sync(0xffffffffu, s, 4);
    s += __shfl_down_sync(0xffffffffu, s, 2);
    s += __shfl_down_sync(0xffffffffu, s, 1);
    return s;
}

// ---------------------------------------------------------------------------
// unified score kernel: one launch, block-range dispatch, branch-free bodies
// ---------------------------------------------------------------------------
__device__ __forceinline__ void nei_body(
    int blk, int lane, int warp,
    const float* __restrict__ nei_node_mem,
    const float* __restrict__ nei_rel_mem,
    const float* __restrict__ head_rel_emb,
    const float* __restrict__ new_emb)
{
    const int gw  = blk * 8 + warp;
    const int sub = lane >> 3;
    const int sl  = lane & 7;

    const int pr  = gw * 8 + sub * 2;     // first row of pair (even)
    const int n   = pr >> 7;
    const int idx = pr & 127;             // even, pair never crosses d
    const int d   = idx >> 3;

    const float4* pa = (const float4*)(nei_node_mem + ((size_t)n * 128 + idx) * Rr);
    const float4* pb = (const float4*)(nei_rel_mem  + ((size_t)n * 128 + idx) * Rr);
    const float4* ph = (const float4*)(head_rel_emb + ((size_t)n * Dd + d) * Rr);
    const float4* pn = (const float4*)(new_emb + (size_t)n * Rr);

    const float4 ne0 = __ldg(&pn[sl]);
    const float4 ne1 = __ldg(&pn[8 + sl]);
    const float4 h0  = __ldg(&ph[sl]);
    const float4 h1  = __ldg(&ph[8 + sl]);

    const float4 a0 = __ldcs(&pa[sl]);
    const float4 a1 = __ldcs(&pa[8 + sl]);
    const float4 a2 = __ldcs(&pa[16 + sl]);
    const float4 a3 = __ldcs(&pa[24 + sl]);
    const float4 b0 = __ldcs(&pb[sl]);
    const float4 b1 = __ldcs(&pb[8 + sl]);
    const float4 b2 = __ldcs(&pb[16 + sl]);
    const float4 b3 = __ldcs(&pb[24 + sl]);

    float4 s0 = make_float4(b0.x + h0.x, b0.y + h0.y, b0.z + h0.z, b0.w + h0.w);
    float4 s1 = make_float4(b1.x + h1.x, b1.y + h1.y, b1.z + h1.z, b1.w + h1.w);
    float4 s2 = make_float4(b2.x + h0.x, b2.y + h0.y, b2.z + h0.z, b2.w + h0.w);
    float4 s3 = make_float4(b3.x + h1.x, b3.y + h1.y, b3.z + h1.z, b3.w + h1.w);

    double r0 = combine8((double)score_part(a0, a1, s0, s1, ne0, ne1));
    double r1 = combine8((double)score_part(a2, a3, s2, s3, ne0, ne1));

    if (sl == 0) g_sc_nei[((size_t)n * 128 + idx) >> 1] = make_double2(r0, r1);
}

__device__ __forceinline__ void head_body(
    int blk, int lane, int warp,
    const float* __restrict__ head_emb,
    const float* __restrict__ head_rel_emb,
    const float* __restrict__ new_emb)
{
    const int gw  = blk * 8 + warp;
    const int sub = lane >> 3;
    const int sl  = lane & 7;

    const int pr = gw * 8 + sub * 2;      // pair of head rows (even d)
    const int n  = pr >> 4;
    const int d  = pr & 15;               // even

    const float4* pa = (const float4*)(head_emb     + ((size_t)n * Dd + d) * Rr);
    const float4* ph = (const float4*)(head_rel_emb + ((size_t)n * Dd + d) * Rr);
    const float4* pn = (const float4*)(new_emb + (size_t)n * Rr);

    const float4 ne0 = __ldg(&pn[sl]);
    const float4 ne1 = __ldg(&pn[8 + sl]);

    const float4 a0 = __ldcs(&pa[sl]);
    const float4 a1 = __ldcs(&pa[8 + sl]);
    const float4 a2 = __ldcs(&pa[16 + sl]);
    const float4 a3 = __ldcs(&pa[24 + sl]);
    const float4 h0 = __ldg(&ph[sl]);
    const float4 h1 = __ldg(&ph[8 + sl]);
    const float4 h2 = __ldg(&ph[16 + sl]);
    const float4 h3 = __ldg(&ph[24 + sl]);

    double r0 = combine8((double)score_part(a0, a1, h0, h1, ne0, ne1));
    double r1 = combine8((double)score_part(a2, a3, h2, h3, ne0, ne1));

    if (sl == 0) g_sc_head[((size_t)n * Dd + d) >> 1] = make_double2(r0, r1);
}

__device__ __forceinline__ void curr_body(
    int blk, int lane, int warp,
    const float* __restrict__ curr_node_mem,
    const float* __restrict__ curr_rel_mem,
    const float* __restrict__ new_emb)
{
    const int gw  = blk * 8 + warp;
    const int sub = lane >> 3;
    const int sl  = lane & 7;

    const int pr = gw * 8 + sub * 2;      // pair of curr rows (even)
    const int n  = pr >> 3;
    const int c  = pr & 7;                // even

    const float4* pa = (const float4*)(curr_node_mem + ((size_t)n * Dd * Cc + c) * Rr);
    const float4* pb = (const float4*)(curr_rel_mem  + ((size_t)n * Dd * Cc + c) * Rr);
    const float4* pn = (const float4*)(new_emb + (size_t)n * Rr);

    const float4 ne0 = __ldg(&pn[sl]);
    const float4 ne1 = __ldg(&pn[8 + sl]);

    const float4 a0 = __ldcs(&pa[sl]);
    const float4 a1 = __ldcs(&pa[8 + sl]);
    const float4 a2 = __ldcs(&pa[16 + sl]);
    const float4 a3 = __ldcs(&pa[24 + sl]);
    const float4 b0 = __ldcs(&pb[sl]);
    const float4 b1 = __ldcs(&pb[8 + sl]);
    const float4 b2 = __ldcs(&pb[16 + sl]);
    const float4 b3 = __ldcs(&pb[24 + sl]);

    double r0 = combine8((double)score_part(a0, a1, b0, b1, ne0, ne1));
    double r1 = combine8((double)score_part(a2, a3, b2, b3, ne0, ne1));

    if (sl == 0) {
        g_sc_curr[(size_t)n * Cc + c]     = r0;
        g_sc_curr[(size_t)n * Cc + c + 1] = r1;
    }
}

__global__ __launch_bounds__(256) void score_kernel(
    const float* __restrict__ curr_node_mem,
    const float* __restrict__ curr_rel_mem,
    const float* __restrict__ nei_node_mem,
    const float* __restrict__ nei_rel_mem,
    const float* __restrict__ head_rel_emb,
    const float* __restrict__ head_emb,
    const float* __restrict__ new_emb)
{
    const int lane = threadIdx.x & 31;
    const int warp = threadIdx.x >> 5;
    const int b = blockIdx.x;

    if (b < NEI_BLOCKS) {
        nei_body(b, lane, warp, nei_node_mem, nei_rel_mem, head_rel_emb, new_emb);
    } else if (b < NEI_BLOCKS + HEAD_BLOCKS) {
        head_body(b - NEI_BLOCKS, lane, warp, head_emb, head_rel_emb, new_emb);
    } else {
        curr_body(b - NEI_BLOCKS - HEAD_BLOCKS, lane, warp,
                  curr_node_mem, curr_rel_mem, new_emb);
    }
}

// ---------------------------------------------------------------------------
// Kernel C: per-n topk (stable) + gather. Block per n, 256 threads.
// ---------------------------------------------------------------------------
__global__ __launch_bounds__(256) void topk_gather_kernel(
    const float* __restrict__ curr_node_mem,
    const float* __restrict__ curr_rel_mem,
    const float* __restrict__ nei_node_mem,
    const float* __restrict__ nei_rel_mem,
    const float* __restrict__ head_rel_emb,
    const float* __restrict__ head_emb,
    float* __restrict__ out_node,
    float* __restrict__ out_rel)
{
    const int n    = blockIdx.x;
    const int t    = threadIdx.x;
    const int w    = t >> 5;
    const int lane = t & 31;

    __shared__ double s_score[NROWS];
    __shared__ int    s_sel[Cc];

    if (t < NROWS) {
        double s;
        if (t < Cc) {
            s = g_sc_curr[(size_t)n * Cc + t];
        } else {
            const int j2 = t - Cc;
            const int d  = j2 / 9;
            const int cc = j2 - d * 9;
            if (cc < Cc) {
                const int idx = d * Cc + cc;
                const double2 p = g_sc_nei[((size_t)n * 128 + idx) >> 1];
                s = (idx & 1) ? p.y : p.x;
            } else {
                const double2 p = g_sc_head[((size_t)n * Dd + d) >> 1];
                s = (d & 1) ? p.y : p.x;
            }
        }
        s_score[t] = s;
    }
    __syncthreads();

    if (w == 0) {
        for (int k = 0; k < Cc; k++) {
            double bs = -1.0;
            int    bj = NROWS;
            for (int j = lane; j < NROWS; j += 32) {
                double s = s_score[j];
                if (s > bs || (s == bs && j < bj)) { bs = s; bj = j; }
            }
            #pragma unroll
            for (int off = 16; off; off >>= 1) {
                double os = __shfl_down_sync(0xffffffffu, bs, off);
                int    oj = __shfl_down_sync(0xffffffffu, bj, off);
                if (os > bs || (os == bs && oj < bj)) { bs = os; bj = oj; }
            }
            bj = __shfl_sync(0xffffffffu, bj, 0);
            if (lane == 0) { s_sel[k] = bj; s_score[bj] = -2.0; }
            __syncwarp();
        }
    }
    __syncthreads();

    // gather: warp w writes output row (n, w)
    // reference: f = n*C + topkind; nn = f/152, col = f%152 (cross-sample)
    const int jsel = s_sel[w];
    const int f    = n * Cc + jsel;
    const int nn   = f / NROWS;
    const int col  = f - nn * NROWS;
    const size_t gDR  = (size_t)nn * Dd * Rr;
    const size_t gDCR = (size_t)nn * Dd * Cc * Rr;

    float2 a, b;
    if (col < Cc) {
        a = ((const float2*)(curr_node_mem + gDCR + (size_t)col * Rr))[lane];
        b = ((const float2*)(curr_rel_mem  + gDCR + (size_t)col * Rr))[lane];
    } else {
        int c2 = col - Cc;
        int d  = c2 / 9;
        int cc = c2 - d * 9;
        float2 h = ((const float2*)(head_rel_emb + gDR + (size_t)d * Rr))[lane];
        if (cc < Cc) {
            a = ((const float2*)(nei_node_mem + gDCR + (size_t)(d * Cc + cc) * Rr))[lane];
            float2 bb = ((const float2*)(nei_rel_mem + gDCR + (size_t)(d * Cc + cc) * Rr))[lane];
            b.x = bb.x + h.x;  b.y = bb.y + h.y;
        } else {
            a = ((const float2*)(head_emb + gDR + (size_t)d * Rr))[lane];
            b = h;
        }
    }
    ((float2*)(out_node + ((size_t)n * Cc + w) * Rr))[lane] = a;
    ((float2*)(out_rel  + ((size_t)n * Cc + w) * Rr))[lane] = b;
}

// ---------------------------------------------------------------------------
extern "C" void kernel_launch(void* const* d_in, const int* in_sizes, int n_in,
                              void* d_out, int out_size)
{
    (void)in_sizes; (void)n_in; (void)out_size;
    const float* curr_emb      = (const float*)d_in[0];
    const float* alpha         = (const float*)d_in[1];
    const float* msg           = (const float*)d_in[2];
    const float* curr_node_mem = (const float*)d_in[3];
    const float* curr_rel_mem  = (const float*)d_in[4];
    const float* nei_node_mem  = (const float*)d_in[5];
    const float* nei_rel_mem   = (const float*)d_in[6];
    const float* head_rel_emb  = (const float*)d_in[7];
    const float* head_emb      = (const float*)d_in[8];

    float* out_emb  = (float*)d_out;                     // N*R
    float* out_node = out_emb  + (size_t)Nn * Rr;        // N*C*R
    float* out_rel  = out_node + (size_t)Nn * Cc * Rr;   // N*C*R

    // A: new_emb
    new_emb_kernel<<<(Nn * Rr) / 256, 256>>>(msg, alpha, curr_emb, out_emb);

    // B: unified scores — one launch, block-range dispatch
    score_kernel<<<B_BLOCKS, 256>>>(curr_node_mem, curr_rel_mem,
                                    nei_node_mem, nei_rel_mem,
                                    head_rel_emb, head_emb, out_emb);

    // C: topk + gather
    topk_gather_kernel<<<Nn, 256>>>(curr_node_mem, curr_rel_mem,
                                    nei_node_mem, nei_rel_mem,
                                    head_rel_emb, head_emb,
                                    out_node, out_rel);
}